// round 3
// baseline (speedup 1.0000x reference)
#include <cuda_runtime.h>
#include <cuda_bf16.h>

// Problem constants
#define B 4
#define L 512
#define E 1024
#define H 128
#define NR (B * L)          // 2048 rows per tensor

// Scratch: hidden activations for rec (rows 0..NR-1) and lig (rows NR..2NR-1)
__device__ __align__(16) float g_hid[2 * NR * H];
__device__ unsigned g_maxu[B];
__device__ int g_done;

typedef unsigned long long ull;

__device__ __forceinline__ float tanh_ap(float x) {
    float y;
    asm("tanh.approx.f32 %0, %1;" : "=f"(y) : "f"(x));
    return y;
}
__device__ __forceinline__ ull pack2(float lo, float hi) {
    ull r; asm("mov.b64 %0, {%1, %2};" : "=l"(r) : "f"(lo), "f"(hi)); return r;
}
__device__ __forceinline__ void unpack2(ull v, float& lo, float& hi) {
    asm("mov.b64 {%0, %1}, %2;" : "=f"(lo), "=f"(hi) : "l"(v));
}
__device__ __forceinline__ ull mul2(ull a, ull b) {
    ull r; asm("mul.rn.f32x2 %0, %1, %2;" : "=l"(r) : "l"(a), "l"(b)); return r;
}
__device__ __forceinline__ ull fma2(ull a, ull b, ull c) {
    ull r; asm("fma.rn.f32x2 %0, %1, %2, %3;" : "=l"(r) : "l"(a), "l"(b), "l"(c)); return r;
}

__device__ __forceinline__ unsigned fenc(float f) {
    unsigned b = __float_as_uint(f);
    return (b & 0x80000000u) ? ~b : (b | 0x80000000u);
}
__device__ __forceinline__ float fdec(unsigned u) {
    return (u & 0x80000000u) ? __uint_as_float(u & 0x7fffffffu)
                             : __uint_as_float(~u);
}

// ---------------------------------------------------------------------------
// Kernel 1: hid = relu(emb @ W1 + b1) for rec and lig. Also resets reduction
// state (g_maxu, g_done) for this replay.
// M-tile 32, N = 128, K-tile 32. 256 threads, 4x4 micro-tile, f32x2 FMA.
// A is stored in smem PRE-SPLATTED: A_sT2[kk][row] = (a, a) so the inner loop
// needs no per-FFMA splat MOVs.
// ---------------------------------------------------------------------------
__global__ __launch_bounds__(256) void gemm_relu_kernel(
    const float* __restrict__ rec, const float* __restrict__ lig,
    const float* __restrict__ W1, const float* __restrict__ b1)
{
    __shared__ __align__(16) ull   A_sT2[32][32];   // [kk][row] splatted, 8KB
    __shared__ __align__(16) float W_s[32][128];    // [kk][col], 16KB

    const int t    = threadIdx.x;
    const int tcol = t & 31;   // float4 column group -> cols 4*tcol..+3
    const int trow = t >> 5;   // row group -> rows 4*trow..+3
    const int row0 = blockIdx.x * 32;

    if (blockIdx.x == 0 && t == 0) {
        g_done = 0;
#pragma unroll
        for (int b = 0; b < B; ++b) g_maxu[b] = 0u;  // below encode of any real
    }

    ull acc[4][2];
#pragma unroll
    for (int u = 0; u < 4; ++u) { acc[u][0] = 0ull; acc[u][1] = 0ull; }

    const int arow = t >> 3;          // 0..31
    const int akc  = (t & 7) * 4;     // 0,4,...,28
    const float* aptr;
    {
        int gr = row0 + arow;
        aptr = (gr < NR) ? (rec + (size_t)gr * E) : (lig + (size_t)(gr - NR) * E);
    }

    for (int k0 = 0; k0 < E; k0 += 32) {
        {
            float4 v = *(const float4*)(aptr + k0 + akc);
            A_sT2[akc + 0][arow] = pack2(v.x, v.x);
            A_sT2[akc + 1][arow] = pack2(v.y, v.y);
            A_sT2[akc + 2][arow] = pack2(v.z, v.z);
            A_sT2[akc + 3][arow] = pack2(v.w, v.w);
        }
        {
            const float4* wsrc = (const float4*)(W1 + (size_t)k0 * H);
            float4* wdst = (float4*)&W_s[0][0];
            wdst[t]       = wsrc[t];
            wdst[t + 256] = wsrc[t + 256];
            wdst[t + 512] = wsrc[t + 512];
            wdst[t + 768] = wsrc[t + 768];
        }
        __syncthreads();
#pragma unroll 8
        for (int kk = 0; kk < 32; ++kk) {
            ulonglong2 a01 = *(const ulonglong2*)&A_sT2[kk][trow * 4];
            ulonglong2 a23 = *(const ulonglong2*)&A_sT2[kk][trow * 4 + 2];
            ulonglong2 wq  = *(const ulonglong2*)&W_s[kk][tcol * 4];
            acc[0][0] = fma2(a01.x, wq.x, acc[0][0]);
            acc[0][1] = fma2(a01.x, wq.y, acc[0][1]);
            acc[1][0] = fma2(a01.y, wq.x, acc[1][0]);
            acc[1][1] = fma2(a01.y, wq.y, acc[1][1]);
            acc[2][0] = fma2(a23.x, wq.x, acc[2][0]);
            acc[2][1] = fma2(a23.x, wq.y, acc[2][1]);
            acc[3][0] = fma2(a23.y, wq.x, acc[3][0]);
            acc[3][1] = fma2(a23.y, wq.y, acc[3][1]);
        }
        __syncthreads();
    }

    float4 bv = ((const float4*)b1)[tcol];
#pragma unroll
    for (int u = 0; u < 4; ++u) {
        int gr = row0 + trow * 4 + u;
        float a0, a1, a2, a3;
        unpack2(acc[u][0], a0, a1);
        unpack2(acc[u][1], a2, a3);
        float4 o;
        o.x = fmaxf(a0 + bv.x, 0.f);
        o.y = fmaxf(a1 + bv.y, 0.f);
        o.z = fmaxf(a2 + bv.z, 0.f);
        o.w = fmaxf(a3 + bv.w, 0.f);
        *(float4*)&g_hid[(size_t)gr * H + tcol * 4] = o;
    }
}

// ---------------------------------------------------------------------------
// Kernel 2: per (i,j) tile, compute S_k(i,j) = sum_h tanh(r_i[h]*l_j[h])*w_k[h]
// for a 32x32 S-tile, combine into 31x31 y-tile, reduce max, atomicMax per
// batch. Last finished block applies sigmoid and writes the output.
// y(p,q) = cb + S00(p-1,q-1)+S01(p-1,q)+S10(p,q-1)+S11(p,q); the maxpool+
// global-max over the 513x513 conv output equals max over p,q in [0,512).
// Inner loop uses mul.f32x2 / fma.f32x2 so MUFU (tanh) is the binding pipe.
// ---------------------------------------------------------------------------
#define TS 31       // y-tile size per block
#define NTILE ((L + TS - 1) / TS)            // 17
#define NBLK  (NTILE * NTILE * B)            // 1156
#define LPAD 132    // padded row stride in floats (conflict-free float4)

__global__ __launch_bounds__(1024) void tile_max_kernel(
    const float* __restrict__ conv_w, const float* __restrict__ conv_b,
    float* __restrict__ out)
{
    __shared__ __align__(16) float r_s[32][LPAD];
    __shared__ __align__(16) float l_s[32][LPAD];
    __shared__ __align__(16) float4 w4_s[H];

    const int tx = threadIdx.x;          // j within tile
    const int ty = threadIdx.y;          // i within tile
    const int t  = ty * 32 + tx;
    const int b  = blockIdx.z;
    const int i0 = blockIdx.y * TS;      // first y-row p of this block
    const int j0 = blockIdx.x * TS;      // first y-col q

    {
        int iload = i0 - 1 + ty;
        int jload = j0 - 1 + ty;
        float4 zz = make_float4(0.f, 0.f, 0.f, 0.f);
        float4 rv = zz, lv = zz;
        if (iload >= 0 && iload < L)
            rv = ((const float4*)(g_hid + (size_t)(b * L + iload) * H))[tx];
        if (jload >= 0 && jload < L)
            lv = ((const float4*)(g_hid + (size_t)(NR + b * L + jload) * H))[tx];
        ((float4*)&r_s[ty][0])[tx] = rv;
        ((float4*)&l_s[ty][0])[tx] = lv;
        if (t < H) w4_s[t] = ((const float4*)conv_w)[t];  // (w00,w01,w10,w11)
    }
    __syncthreads();

    ull sA = 0ull, sB = 0ull;            // (s0,s1), (s2,s3)
    const ulonglong2* rp = (const ulonglong2*)&r_s[ty][0];
    const ulonglong2* lp = (const ulonglong2*)&l_s[tx][0];
    const ulonglong2* wp = (const ulonglong2*)&w4_s[0];
#pragma unroll 8
    for (int h4 = 0; h4 < H / 4; ++h4) {
        ulonglong2 rq = rp[h4];
        ulonglong2 lq = lp[h4];
        ull pA = mul2(rq.x, lq.x);
        ull pB = mul2(rq.y, lq.y);
        float x0, x1, x2, x3;
        unpack2(pA, x0, x1);
        unpack2(pB, x2, x3);
        float t0 = tanh_ap(x0), t1 = tanh_ap(x1);
        float t2 = tanh_ap(x2), t3 = tanh_ap(x3);
        ulonglong2 w0 = wp[4 * h4 + 0];
        ulonglong2 w1 = wp[4 * h4 + 1];
        ulonglong2 w2 = wp[4 * h4 + 2];
        ulonglong2 w3 = wp[4 * h4 + 3];
        ull T0 = pack2(t0, t0), T1 = pack2(t1, t1);
        ull T2 = pack2(t2, t2), T3 = pack2(t3, t3);
        sA = fma2(T0, w0.x, sA); sB = fma2(T0, w0.y, sB);
        sA = fma2(T1, w1.x, sA); sB = fma2(T1, w1.y, sB);
        sA = fma2(T2, w2.x, sA); sB = fma2(T2, w2.y, sB);
        sA = fma2(T3, w3.x, sA); sB = fma2(T3, w3.y, sB);
    }
    __syncthreads();  // everyone done reading r_s/l_s

    // S tile aliases r_s storage: 32 x 33 float4 = 16896 B = sizeof(r_s)
    float4* S = (float4*)&r_s[0][0];
    {
        float s0, s1, s2, s3;
        unpack2(sA, s0, s1);
        unpack2(sB, s2, s3);
        S[ty * 33 + tx] = make_float4(s0, s1, s2, s3);
    }
    __syncthreads();

    float m = -3.4e38f;
    if (tx < TS && ty < TS) {
        int p = i0 + ty, q = j0 + tx;
        if (p < L && q < L) {
            float4 a  = S[ty * 33 + tx];             // S00(p-1,q-1)
            float4 bq = S[ty * 33 + tx + 1];         // S01(p-1,q)
            float4 c  = S[(ty + 1) * 33 + tx];       // S10(p,q-1)
            float4 d  = S[(ty + 1) * 33 + tx + 1];   // S11(p,q)
            m = conv_b[0] + a.x + bq.y + c.z + d.w;
        }
    }

    // block max reduce (scratch aliases l_s, free after the h-loop sync)
#pragma unroll
    for (int o = 16; o > 0; o >>= 1)
        m = fmaxf(m, __shfl_xor_sync(0xffffffffu, m, o));
    float* red = &l_s[0][0];
    if (tx == 0) red[ty] = m;
    __syncthreads();
    if (ty == 0) {
        float v = red[tx];
#pragma unroll
        for (int o = 16; o > 0; o >>= 1)
            v = fmaxf(v, __shfl_xor_sync(0xffffffffu, v, o));
        if (tx == 0) {
            atomicMax(&g_maxu[b], fenc(v));
            __threadfence();
            int done = atomicAdd(&g_done, 1);
            if (done == NBLK - 1) {
                // last block: finalize sigmoid(max) -> out
#pragma unroll
                for (int bb = 0; bb < B; ++bb) {
                    unsigned u = atomicMax(&g_maxu[bb], 0u);  // atomic read
                    float mm = fdec(u);
                    out[bb] = 1.f / (1.f + expf(-mm));
                }
            }
        }
    }
}

// ---------------------------------------------------------------------------
extern "C" void kernel_launch(void* const* d_in, const int* in_sizes, int n_in,
                              void* d_out, int out_size)
{
    // Bind by size where unambiguous; rec/lig are the two equal-size large
    // arrays, taken in metadata order.
    const float *rec = 0, *lig = 0, *W1 = 0, *b1 = 0, *conv_w = 0, *conv_b = 0;
    for (int i = 0; i < n_in; ++i) {
        int n = in_sizes[i];
        const float* p = (const float*)d_in[i];
        if (n == B * L * E)      { if (!rec) rec = p; else lig = p; }
        else if (n == E * H)     W1 = p;
        else if (n == H)         b1 = p;
        else if (n == H * 4)     conv_w = p;
        else if (n == 1)         conv_b = p;
    }
    float* out = (float*)d_out;

    gemm_relu_kernel<<<2 * NR / 32, 256>>>(rec, lig, W1, b1);
    dim3 g2(NTILE, NTILE, B);  // 17 x 17 x 4
    tile_max_kernel<<<g2, dim3(32, 32)>>>(conv_w, conv_b, out);
}

// round 4
// speedup vs baseline: 1.2814x; 1.2814x over previous
#include <cuda_runtime.h>
#include <cuda_bf16.h>

// Problem constants
#define B 4
#define L 512
#define E 1024
#define H 128
#define NR (B * L)          // 2048 rows per tensor

__device__ __align__(16) float g_hid[2 * NR * H];
__device__ unsigned g_maxu[B];
__device__ int g_done;

typedef unsigned long long ull;

__device__ __forceinline__ float tanh_ap(float x) {
    float y;
    asm("tanh.approx.f32 %0, %1;" : "=f"(y) : "f"(x));
    return y;
}
__device__ __forceinline__ ull pack2(float lo, float hi) {
    ull r; asm("mov.b64 %0, {%1, %2};" : "=l"(r) : "f"(lo), "f"(hi)); return r;
}
__device__ __forceinline__ void unpack2(ull v, float& lo, float& hi) {
    asm("mov.b64 {%0, %1}, %2;" : "=f"(lo), "=f"(hi) : "l"(v));
}
__device__ __forceinline__ ull mul2(ull a, ull b) {
    ull r; asm("mul.rn.f32x2 %0, %1, %2;" : "=l"(r) : "l"(a), "l"(b)); return r;
}
__device__ __forceinline__ ull fma2(ull a, ull b, ull c) {
    ull r; asm("fma.rn.f32x2 %0, %1, %2, %3;" : "=l"(r) : "l"(a), "l"(b), "l"(c)); return r;
}

__device__ __forceinline__ unsigned fenc(float f) {
    unsigned b = __float_as_uint(f);
    return (b & 0x80000000u) ? ~b : (b | 0x80000000u);
}
__device__ __forceinline__ float fdec(unsigned u) {
    return (u & 0x80000000u) ? __uint_as_float(u & 0x7fffffffu)
                             : __uint_as_float(~u);
}

// ---------------------------------------------------------------------------
// Kernel 1: hid = relu(emb @ W1 + b1). Double-buffered smem, K-tile 16,
// one barrier per tile. M-tile 32, 256 threads, 4 rows x 4 cols per thread,
// f32x2 FMA with pre-splatted A in smem. Also resets reduction state.
// ---------------------------------------------------------------------------
#define KT 16
#define NT (E / KT)   // 64

__global__ __launch_bounds__(256) void gemm_relu_kernel(
    const float* __restrict__ rec, const float* __restrict__ lig,
    const float* __restrict__ W1, const float* __restrict__ b1)
{
    __shared__ __align__(16) ull   A2[2][KT][32];    // 4KB each buf
    __shared__ __align__(16) float Ws[2][KT][128];   // 8KB each buf

    const int t    = threadIdx.x;
    const int tcol = t & 31;   // float4 col group -> cols 4*tcol..+3
    const int trow = t >> 5;   // row group -> rows 4*trow..+3
    const int row0 = blockIdx.x * 32;

    if (blockIdx.x == 0 && t == 0) {
        g_done = 0;
#pragma unroll
        for (int b = 0; b < B; ++b) g_maxu[b] = 0u;
    }

    const int arow = t >> 2;          // 0..63 (only t<128 used: 0..31)
    const int akc  = (t & 3) * 4;     // 0,4,8,12
    const float* aptr = 0;
    if (t < 128) {
        int gr = row0 + arow;
        aptr = (gr < NR) ? (rec + (size_t)gr * E) : (lig + (size_t)(gr - NR) * E);
    }

    ull acc[4][2];
#pragma unroll
    for (int u = 0; u < 4; ++u) { acc[u][0] = 0ull; acc[u][1] = 0ull; }

    // tile loader: gmem -> smem buf
    auto load_tile = [&](int buf, int k0) {
        if (t < 128) {
            float4 v = *(const float4*)(aptr + k0 + akc);
            A2[buf][akc + 0][arow] = pack2(v.x, v.x);
            A2[buf][akc + 1][arow] = pack2(v.y, v.y);
            A2[buf][akc + 2][arow] = pack2(v.z, v.z);
            A2[buf][akc + 3][arow] = pack2(v.w, v.w);
        }
        const float4* wsrc = (const float4*)(W1 + (size_t)k0 * H);
        float4* wd = (float4*)&Ws[buf][0][0];
        wd[t]       = wsrc[t];
        wd[t + 256] = wsrc[t + 256];
    };

    load_tile(0, 0);
    __syncthreads();

    for (int kt = 0; kt < NT; ++kt) {
        int cur = kt & 1;
        if (kt + 1 < NT) load_tile(cur ^ 1, (kt + 1) * KT);
#pragma unroll
        for (int kk = 0; kk < KT; ++kk) {
            ulonglong2 a01 = *(const ulonglong2*)&A2[cur][kk][trow * 4];
            ulonglong2 a23 = *(const ulonglong2*)&A2[cur][kk][trow * 4 + 2];
            ulonglong2 wq  = *(const ulonglong2*)&Ws[cur][kk][tcol * 4];
            acc[0][0] = fma2(a01.x, wq.x, acc[0][0]);
            acc[0][1] = fma2(a01.x, wq.y, acc[0][1]);
            acc[1][0] = fma2(a01.y, wq.x, acc[1][0]);
            acc[1][1] = fma2(a01.y, wq.y, acc[1][1]);
            acc[2][0] = fma2(a23.x, wq.x, acc[2][0]);
            acc[2][1] = fma2(a23.x, wq.y, acc[2][1]);
            acc[3][0] = fma2(a23.y, wq.x, acc[3][0]);
            acc[3][1] = fma2(a23.y, wq.y, acc[3][1]);
        }
        __syncthreads();
    }

    float4 bv = ((const float4*)b1)[tcol];
#pragma unroll
    for (int u = 0; u < 4; ++u) {
        int gr = row0 + trow * 4 + u;
        float a0, a1, a2, a3;
        unpack2(acc[u][0], a0, a1);
        unpack2(acc[u][1], a2, a3);
        float4 o;
        o.x = fmaxf(a0 + bv.x, 0.f);
        o.y = fmaxf(a1 + bv.y, 0.f);
        o.z = fmaxf(a2 + bv.z, 0.f);
        o.w = fmaxf(a3 + bv.w, 0.f);
        *(float4*)&g_hid[(size_t)gr * H + tcol * 4] = o;
    }
}

// ---------------------------------------------------------------------------
// Kernel 2: 256 threads (16x16), each computes a 2x2 micro-tile of S-points
// (rows ty/ty+16, cols tx/tx+16) -> 32x32 S-tile, 31x31 y-tile, block max,
// atomicMax per batch; last block finalizes sigmoid -> out.
// ---------------------------------------------------------------------------
#define TS 31
#define NTILE ((L + TS - 1) / TS)            // 17
#define NBLK  (NTILE * NTILE * B)            // 1156
#define LPAD 132

__global__ __launch_bounds__(256) void tile_max_kernel(
    const float* __restrict__ conv_w, const float* __restrict__ conv_b,
    float* __restrict__ out)
{
    __shared__ __align__(16) float r_s[32][LPAD];   // 16896 B (aliased by S)
    __shared__ __align__(16) float l_s[32][LPAD];   // 16896 B
    __shared__ __align__(16) float4 w4_s[H];        // 2 KB

    const int tx = threadIdx.x;          // 0..15
    const int ty = threadIdx.y;          // 0..15
    const int t  = ty * 16 + tx;
    const int b  = blockIdx.z;
    const int i0 = blockIdx.y * TS;
    const int j0 = blockIdx.x * TS;

    // Load 32 r-rows and 32 l-rows (with halo at -1) + conv weights
    {
        int lr  = t >> 3;          // 0..31 row
        int lc4 = t & 7;           // base float4 col
        int iload = i0 - 1 + lr;
        int jload = j0 - 1 + lr;
        const float4* rsrc = (const float4*)(g_hid + (size_t)(b * L + iload) * H);
        const float4* lsrc = (const float4*)(g_hid + (size_t)(NR + b * L + jload) * H);
        bool rok = (iload >= 0 && iload < L);
        bool lok = (jload >= 0 && jload < L);
        float4 zz = make_float4(0.f, 0.f, 0.f, 0.f);
        float4* rdst = (float4*)&r_s[lr][0];
        float4* ldst = (float4*)&l_s[lr][0];
#pragma unroll
        for (int k = 0; k < 4; ++k) {
            int c4 = lc4 + 8 * k;
            rdst[c4] = rok ? rsrc[c4] : zz;
            ldst[c4] = lok ? lsrc[c4] : zz;
        }
        if (t < H) w4_s[t] = ((const float4*)conv_w)[t];   // (w00,w01,w10,w11)
    }
    __syncthreads();

    // accumulators: 4 points x (taps01, taps23) packed f32x2
    ull a00A = 0, a00B = 0, a01A = 0, a01B = 0;
    ull a10A = 0, a10B = 0, a11A = 0, a11B = 0;
    const ulonglong2* rp0 = (const ulonglong2*)&r_s[ty][0];
    const ulonglong2* rp1 = (const ulonglong2*)&r_s[ty + 16][0];
    const ulonglong2* lp0 = (const ulonglong2*)&l_s[tx][0];
    const ulonglong2* lp1 = (const ulonglong2*)&l_s[tx + 16][0];
    const ulonglong2* wp  = (const ulonglong2*)&w4_s[0];

#define COMBO(Rv, Lv, AA, BB)                                              \
    {                                                                      \
        ull pA = mul2(Rv.x, Lv.x);                                         \
        ull pB = mul2(Rv.y, Lv.y);                                         \
        float x0, x1, x2, x3;                                              \
        unpack2(pA, x0, x1);                                               \
        unpack2(pB, x2, x3);                                               \
        float t0 = tanh_ap(x0), t1 = tanh_ap(x1);                          \
        float t2 = tanh_ap(x2), t3 = tanh_ap(x3);                          \
        ull T0 = pack2(t0, t0), T1 = pack2(t1, t1);                        \
        ull T2 = pack2(t2, t2), T3 = pack2(t3, t3);                        \
        AA = fma2(T0, W0.x, AA); BB = fma2(T0, W0.y, BB);                  \
        AA = fma2(T1, W1.x, AA); BB = fma2(T1, W1.y, BB);                  \
        AA = fma2(T2, W2.x, AA); BB = fma2(T2, W2.y, BB);                  \
        AA = fma2(T3, W3.x, AA); BB = fma2(T3, W3.y, BB);                  \
    }

#pragma unroll 4
    for (int h4 = 0; h4 < H / 4; ++h4) {
        ulonglong2 R0 = rp0[h4], R1 = rp1[h4];
        ulonglong2 L0 = lp0[h4], L1 = lp1[h4];
        ulonglong2 W0 = wp[4 * h4 + 0];
        ulonglong2 W1 = wp[4 * h4 + 1];
        ulonglong2 W2 = wp[4 * h4 + 2];
        ulonglong2 W3 = wp[4 * h4 + 3];
        COMBO(R0, L0, a00A, a00B);
        COMBO(R0, L1, a01A, a01B);
        COMBO(R1, L0, a10A, a10B);
        COMBO(R1, L1, a11A, a11B);
    }
    __syncthreads();   // done reading r_s/l_s

    // S tile aliases r_s: 32 x 33 float4 = 16896 B
    float4* S = (float4*)&r_s[0][0];
    {
        float s0, s1, s2, s3;
        unpack2(a00A, s0, s1); unpack2(a00B, s2, s3);
        S[ty * 33 + tx]             = make_float4(s0, s1, s2, s3);
        unpack2(a01A, s0, s1); unpack2(a01B, s2, s3);
        S[ty * 33 + tx + 16]        = make_float4(s0, s1, s2, s3);
        unpack2(a10A, s0, s1); unpack2(a10B, s2, s3);
        S[(ty + 16) * 33 + tx]      = make_float4(s0, s1, s2, s3);
        unpack2(a11A, s0, s1); unpack2(a11B, s2, s3);
        S[(ty + 16) * 33 + tx + 16] = make_float4(s0, s1, s2, s3);
    }
    __syncthreads();

    const float cb = conv_b[0];
    float m = -3.4e38f;
#pragma unroll
    for (int dy = 0; dy < 2; ++dy) {
#pragma unroll
        for (int dx = 0; dx < 2; ++dx) {
            int pp = ty + dy * 16, qq = tx + dx * 16;
            int p = i0 + pp, q = j0 + qq;
            if (pp < TS && qq < TS && p < L && q < L) {
                float4 a  = S[pp * 33 + qq];             // S00(p-1,q-1)
                float4 bq = S[pp * 33 + qq + 1];         // S01(p-1,q)
                float4 c  = S[(pp + 1) * 33 + qq];       // S10(p,q-1)
                float4 d  = S[(pp + 1) * 33 + qq + 1];   // S11(p,q)
                float y = cb + a.x + bq.y + c.z + d.w;
                m = fmaxf(m, y);
            }
        }
    }

    // block max reduce (scratch aliases l_s, free now)
#pragma unroll
    for (int o = 16; o > 0; o >>= 1)
        m = fmaxf(m, __shfl_xor_sync(0xffffffffu, m, o));
    float* red = &l_s[0][0];
    int wid = t >> 5, lid = t & 31;
    if (lid == 0) red[wid] = m;
    __syncthreads();
    if (t < 32) {
        float v = (t < 8) ? red[t] : -3.4e38f;
#pragma unroll
        for (int o = 4; o > 0; o >>= 1)
            v = fmaxf(v, __shfl_xor_sync(0xffffffffu, v, o));
        if (t == 0) {
            atomicMax(&g_maxu[b], fenc(v));
            __threadfence();
            int done = atomicAdd(&g_done, 1);
            if (done == NBLK - 1) {
#pragma unroll
                for (int bb = 0; bb < B; ++bb) {
                    unsigned u = atomicMax(&g_maxu[bb], 0u);  // atomic read
                    float mm = fdec(u);
                    out[bb] = 1.f / (1.f + expf(-mm));
                }
            }
        }
    }
}

// ---------------------------------------------------------------------------
extern "C" void kernel_launch(void* const* d_in, const int* in_sizes, int n_in,
                              void* d_out, int out_size)
{
    const float *rec = 0, *lig = 0, *W1 = 0, *b1 = 0, *conv_w = 0, *conv_b = 0;
    for (int i = 0; i < n_in; ++i) {
        int n = in_sizes[i];
        const float* p = (const float*)d_in[i];
        if (n == B * L * E)      { if (!rec) rec = p; else lig = p; }
        else if (n == E * H)     W1 = p;
        else if (n == H)         b1 = p;
        else if (n == H * 4)     conv_w = p;
        else if (n == 1)         conv_b = p;
    }
    float* out = (float*)d_out;

    gemm_relu_kernel<<<2 * NR / 32, 256>>>(rec, lig, W1, b1);
    dim3 g2(NTILE, NTILE, B);  // 17 x 17 x 4
    tile_max_kernel<<<g2, dim3(16, 16)>>>(conv_w, conv_b, out);
}

// round 5
// speedup vs baseline: 1.2863x; 1.0038x over previous
#include <cuda_runtime.h>
#include <cuda_bf16.h>

// Problem constants
#define B 4
#define L 512
#define E 1024
#define H 128
#define NR (B * L)          // 2048 rows per tensor

__device__ __align__(16) float g_hid[2 * NR * H];
__device__ unsigned g_maxu[B];
__device__ int g_done;

typedef unsigned long long ull;

__device__ __forceinline__ float tanh_ap(float x) {
    float y;
    asm("tanh.approx.f32 %0, %1;" : "=f"(y) : "f"(x));
    return y;
}
__device__ __forceinline__ ull pack2(float lo, float hi) {
    ull r; asm("mov.b64 %0, {%1, %2};" : "=l"(r) : "f"(lo), "f"(hi)); return r;
}
__device__ __forceinline__ void unpack2(ull v, float& lo, float& hi) {
    asm("mov.b64 {%0, %1}, %2;" : "=f"(lo), "=f"(hi) : "l"(v));
}
__device__ __forceinline__ ull mul2(ull a, ull b) {
    ull r; asm("mul.rn.f32x2 %0, %1, %2;" : "=l"(r) : "l"(a), "l"(b)); return r;
}
__device__ __forceinline__ ull fma2(ull a, ull b, ull c) {
    ull r; asm("fma.rn.f32x2 %0, %1, %2, %3;" : "=l"(r) : "l"(a), "l"(b), "l"(c)); return r;
}

__device__ __forceinline__ unsigned fenc(float f) {
    unsigned b = __float_as_uint(f);
    return (b & 0x80000000u) ? ~b : (b | 0x80000000u);
}
__device__ __forceinline__ float fdec(unsigned u) {
    return (u & 0x80000000u) ? __uint_as_float(u & 0x7fffffffu)
                             : __uint_as_float(~u);
}

// ---------------------------------------------------------------------------
// Kernel 1: hid = relu(emb @ W1 + b1).
// M-tile 16, 256 blocks (all SMs busy), K-tile 32 double-buffered so the
// per-tile compute (~1024 cyc/SMSP at 4 warps) hides the ~600-cyc LDG.
// 256 threads; micro-tile 2 rows x 4 cols, f32x2 FMA. A rows are broadcast
// LDS (whole warp same row pair) + register splat.
// ---------------------------------------------------------------------------
#define KT 32
#define NT (E / KT)      // 32 tiles
#define MT 16

__global__ __launch_bounds__(256) void gemm_relu_kernel(
    const float* __restrict__ rec, const float* __restrict__ lig,
    const float* __restrict__ W1, const float* __restrict__ b1)
{
    __shared__ __align__(16) float A_s[2][MT][KT];    // 2KB per buf
    __shared__ __align__(16) float Ws[2][KT][128];    // 16KB per buf

    const int t     = threadIdx.x;
    const int tcol  = t & 31;    // float4 col group -> cols 4*tcol..+3
    const int trowg = t >> 5;    // 0..7 -> rows 2*trowg, 2*trowg+1
    const int row0  = blockIdx.x * MT;

    if (blockIdx.x == 0 && t == 0) {
        g_done = 0;
#pragma unroll
        for (int b = 0; b < B; ++b) g_maxu[b] = 0u;
    }

    // A loader mapping (t < 128): 8 threads per row, coalesced float4
    const int arow = t >> 3;          // 0..15
    const int akc  = (t & 7) * 4;     // 0,4,...,28
    const float* aptr = 0;
    if (t < 128) {
        int gr = row0 + arow;
        aptr = (gr < NR) ? (rec + (size_t)gr * E) : (lig + (size_t)(gr - NR) * E);
    }

    ull acc[2][2];
    acc[0][0] = acc[0][1] = acc[1][0] = acc[1][1] = 0ull;

    auto load_tile = [&](int buf, int k0) {
        if (t < 128) {
            float4 v = *(const float4*)(aptr + k0 + akc);
            *(float4*)&A_s[buf][arow][akc] = v;
        }
        const float4* wsrc = (const float4*)(W1 + (size_t)k0 * H);
        float4* wd = (float4*)&Ws[buf][0][0];
        wd[t]       = wsrc[t];
        wd[t + 256] = wsrc[t + 256];
        wd[t + 512] = wsrc[t + 512];
        wd[t + 768] = wsrc[t + 768];
    };

    load_tile(0, 0);
    __syncthreads();

    for (int kt = 0; kt < NT; ++kt) {
        int cur = kt & 1;
        if (kt + 1 < NT) load_tile(cur ^ 1, (kt + 1) * KT);
#pragma unroll
        for (int kk = 0; kk < KT; ++kk) {
            float a0 = A_s[cur][trowg * 2 + 0][kk];     // broadcast LDS
            float a1 = A_s[cur][trowg * 2 + 1][kk];     // broadcast LDS
            ulonglong2 wq = *(const ulonglong2*)&Ws[cur][kk][tcol * 4];
            ull A0 = pack2(a0, a0);
            ull A1 = pack2(a1, a1);
            acc[0][0] = fma2(A0, wq.x, acc[0][0]);
            acc[0][1] = fma2(A0, wq.y, acc[0][1]);
            acc[1][0] = fma2(A1, wq.x, acc[1][0]);
            acc[1][1] = fma2(A1, wq.y, acc[1][1]);
        }
        __syncthreads();
    }

    float4 bv = ((const float4*)b1)[tcol];
#pragma unroll
    for (int u = 0; u < 2; ++u) {
        int gr = row0 + trowg * 2 + u;
        float a0, a1, a2, a3;
        unpack2(acc[u][0], a0, a1);
        unpack2(acc[u][1], a2, a3);
        float4 o;
        o.x = fmaxf(a0 + bv.x, 0.f);
        o.y = fmaxf(a1 + bv.y, 0.f);
        o.z = fmaxf(a2 + bv.z, 0.f);
        o.w = fmaxf(a3 + bv.w, 0.f);
        *(float4*)&g_hid[(size_t)gr * H + tcol * 4] = o;
    }
}

// ---------------------------------------------------------------------------
// Kernel 2: 256 threads (16x16), each computes a 2x2 micro-tile of S-points
// (rows ty/ty+16, cols tx/tx+16) -> 32x32 S-tile, 31x31 y-tile, block max,
// atomicMax per batch; last block finalizes sigmoid -> out.
// ---------------------------------------------------------------------------
#define TS 31
#define NTILE ((L + TS - 1) / TS)            // 17
#define NBLK  (NTILE * NTILE * B)            // 1156
#define LPAD 132

__global__ __launch_bounds__(256) void tile_max_kernel(
    const float* __restrict__ conv_w, const float* __restrict__ conv_b,
    float* __restrict__ out)
{
    __shared__ __align__(16) float r_s[32][LPAD];   // 16896 B (aliased by S)
    __shared__ __align__(16) float l_s[32][LPAD];   // 16896 B
    __shared__ __align__(16) float4 w4_s[H];        // 2 KB

    const int tx = threadIdx.x;          // 0..15
    const int ty = threadIdx.y;          // 0..15
    const int t  = ty * 16 + tx;
    const int b  = blockIdx.z;
    const int i0 = blockIdx.y * TS;
    const int j0 = blockIdx.x * TS;

    {
        int lr  = t >> 3;          // 0..31 row
        int lc4 = t & 7;           // base float4 col
        int iload = i0 - 1 + lr;
        int jload = j0 - 1 + lr;
        const float4* rsrc = (const float4*)(g_hid + (size_t)(b * L + iload) * H);
        const float4* lsrc = (const float4*)(g_hid + (size_t)(NR + b * L + jload) * H);
        bool rok = (iload >= 0 && iload < L);
        bool lok = (jload >= 0 && jload < L);
        float4 zz = make_float4(0.f, 0.f, 0.f, 0.f);
        float4* rdst = (float4*)&r_s[lr][0];
        float4* ldst = (float4*)&l_s[lr][0];
#pragma unroll
        for (int k = 0; k < 4; ++k) {
            int c4 = lc4 + 8 * k;
            rdst[c4] = rok ? rsrc[c4] : zz;
            ldst[c4] = lok ? lsrc[c4] : zz;
        }
        if (t < H) w4_s[t] = ((const float4*)conv_w)[t];   // (w00,w01,w10,w11)
    }
    __syncthreads();

    ull a00A = 0, a00B = 0, a01A = 0, a01B = 0;
    ull a10A = 0, a10B = 0, a11A = 0, a11B = 0;
    const ulonglong2* rp0 = (const ulonglong2*)&r_s[ty][0];
    const ulonglong2* rp1 = (const ulonglong2*)&r_s[ty + 16][0];
    const ulonglong2* lp0 = (const ulonglong2*)&l_s[tx][0];
    const ulonglong2* lp1 = (const ulonglong2*)&l_s[tx + 16][0];
    const ulonglong2* wp  = (const ulonglong2*)&w4_s[0];

#define COMBO(Rv, Lv, AA, BB)                                              \
    {                                                                      \
        ull pA = mul2(Rv.x, Lv.x);                                         \
        ull pB = mul2(Rv.y, Lv.y);                                         \
        float x0, x1, x2, x3;                                              \
        unpack2(pA, x0, x1);                                               \
        unpack2(pB, x2, x3);                                               \
        float t0 = tanh_ap(x0), t1 = tanh_ap(x1);                          \
        float t2 = tanh_ap(x2), t3 = tanh_ap(x3);                          \
        ull T0 = pack2(t0, t0), T1 = pack2(t1, t1);                        \
        ull T2 = pack2(t2, t2), T3 = pack2(t3, t3);                        \
        AA = fma2(T0, W0.x, AA); BB = fma2(T0, W0.y, BB);                  \
        AA = fma2(T1, W1.x, AA); BB = fma2(T1, W1.y, BB);                  \
        AA = fma2(T2, W2.x, AA); BB = fma2(T2, W2.y, BB);                  \
        AA = fma2(T3, W3.x, AA); BB = fma2(T3, W3.y, BB);                  \
    }

#pragma unroll 4
    for (int h4 = 0; h4 < H / 4; ++h4) {
        ulonglong2 R0 = rp0[h4], R1 = rp1[h4];
        ulonglong2 L0 = lp0[h4], L1 = lp1[h4];
        ulonglong2 W0 = wp[4 * h4 + 0];
        ulonglong2 W1 = wp[4 * h4 + 1];
        ulonglong2 W2 = wp[4 * h4 + 2];
        ulonglong2 W3 = wp[4 * h4 + 3];
        COMBO(R0, L0, a00A, a00B);
        COMBO(R0, L1, a01A, a01B);
        COMBO(R1, L0, a10A, a10B);
        COMBO(R1, L1, a11A, a11B);
    }
    __syncthreads();   // done reading r_s/l_s

    float4* S = (float4*)&r_s[0][0];    // 32 x 33 float4 aliases r_s
    {
        float s0, s1, s2, s3;
        unpack2(a00A, s0, s1); unpack2(a00B, s2, s3);
        S[ty * 33 + tx]             = make_float4(s0, s1, s2, s3);
        unpack2(a01A, s0, s1); unpack2(a01B, s2, s3);
        S[ty * 33 + tx + 16]        = make_float4(s0, s1, s2, s3);
        unpack2(a10A, s0, s1); unpack2(a10B, s2, s3);
        S[(ty + 16) * 33 + tx]      = make_float4(s0, s1, s2, s3);
        unpack2(a11A, s0, s1); unpack2(a11B, s2, s3);
        S[(ty + 16) * 33 + tx + 16] = make_float4(s0, s1, s2, s3);
    }
    __syncthreads();

    const float cb = conv_b[0];
    float m = -3.4e38f;
#pragma unroll
    for (int dy = 0; dy < 2; ++dy) {
#pragma unroll
        for (int dx = 0; dx < 2; ++dx) {
            int pp = ty + dy * 16, qq = tx + dx * 16;
            int p = i0 + pp, q = j0 + qq;
            if (pp < TS && qq < TS && p < L && q < L) {
                float4 a  = S[pp * 33 + qq];
                float4 bq = S[pp * 33 + qq + 1];
                float4 c  = S[(pp + 1) * 33 + qq];
                float4 d  = S[(pp + 1) * 33 + qq + 1];
                float y = cb + a.x + bq.y + c.z + d.w;
                m = fmaxf(m, y);
            }
        }
    }

#pragma unroll
    for (int o = 16; o > 0; o >>= 1)
        m = fmaxf(m, __shfl_xor_sync(0xffffffffu, m, o));
    float* red = &l_s[0][0];
    int wid = t >> 5, lid = t & 31;
    if (lid == 0) red[wid] = m;
    __syncthreads();
    if (t < 32) {
        float v = (t < 8) ? red[t] : -3.4e38f;
#pragma unroll
        for (int o = 4; o > 0; o >>= 1)
            v = fmaxf(v, __shfl_xor_sync(0xffffffffu, v, o));
        if (t == 0) {
            atomicMax(&g_maxu[b], fenc(v));
            __threadfence();
            int done = atomicAdd(&g_done, 1);
            if (done == NBLK - 1) {
#pragma unroll
                for (int bb = 0; bb < B; ++bb) {
                    unsigned u = atomicMax(&g_maxu[bb], 0u);  // atomic read
                    float mm = fdec(u);
                    out[bb] = 1.f / (1.f + expf(-mm));
                }
            }
        }
    }
}

// ---------------------------------------------------------------------------
extern "C" void kernel_launch(void* const* d_in, const int* in_sizes, int n_in,
                              void* d_out, int out_size)
{
    const float *rec = 0, *lig = 0, *W1 = 0, *b1 = 0, *conv_w = 0, *conv_b = 0;
    for (int i = 0; i < n_in; ++i) {
        int n = in_sizes[i];
        const float* p = (const float*)d_in[i];
        if (n == B * L * E)      { if (!rec) rec = p; else lig = p; }
        else if (n == E * H)     W1 = p;
        else if (n == H)         b1 = p;
        else if (n == H * 4)     conv_w = p;
        else if (n == 1)         conv_b = p;
    }
    float* out = (float*)d_out;

    gemm_relu_kernel<<<2 * NR / MT, 256>>>(rec, lig, W1, b1);
    dim3 g2(NTILE, NTILE, B);  // 17 x 17 x 4
    tile_max_kernel<<<g2, dim3(16, 16)>>>(conv_w, conv_b, out);
}